// round 1
// baseline (speedup 1.0000x reference)
#include <cuda_runtime.h>
#include <cuda_bf16.h>
#include <cstddef>

// Problem constants
#define DIMC   768
#define NHEADS 12
#define HDIM   64
#define BATCH  8
#define LQ     1024
#define LKV    1024
#define SCALE  0.125f   // 64^-0.5

// Scratch (BSS device globals; no runtime allocation)
__device__ float g_Q [(size_t)BATCH * LQ  * DIMC];          // (B*Lq, 768)  col = h*64+d
__device__ float g_KV[(size_t)BATCH * LKV * 2 * DIMC];      // (B*Lkv,1536) [0:768)=K, [768:1536)=V
__device__ float g_O [(size_t)BATCH * LQ  * DIMC];          // attention output pre-proj

// ---------------------------------------------------------------------------
// C[M,N] = A[M,K] @ W[N,K]^T (+ optional bias). 128x128x16 tile, 8x8 microtile.
// ---------------------------------------------------------------------------
__global__ __launch_bounds__(256)
void gemm_nt(const float* __restrict__ A, const float* __restrict__ W,
             const float* __restrict__ bias, float* __restrict__ C,
             int M, int N, int K)
{
    __shared__ float As[16][128];
    __shared__ float Ws[16][128];

    const int tid = threadIdx.x;
    const int tx = tid & 15;        // 0..15 -> n microtile
    const int ty = tid >> 4;        // 0..15 -> m microtile
    const int m0 = blockIdx.y * 128;
    const int n0 = blockIdx.x * 128;

    float acc[8][8];
#pragma unroll
    for (int i = 0; i < 8; i++)
#pragma unroll
        for (int j = 0; j < 8; j++) acc[i][j] = 0.f;

    const int lrow = tid >> 1;          // 0..127
    const int lk   = (tid & 1) * 8;     // 0 or 8
    const float* Ap = A + (size_t)(m0 + lrow) * K + lk;
    const float* Wp = W + (size_t)(n0 + lrow) * K + lk;

    for (int k0 = 0; k0 < K; k0 += 16) {
        float4 a0 = *(const float4*)(Ap + k0);
        float4 a1 = *(const float4*)(Ap + k0 + 4);
        float4 w0 = *(const float4*)(Wp + k0);
        float4 w1 = *(const float4*)(Wp + k0 + 4);
        __syncthreads();
        As[lk+0][lrow] = a0.x; As[lk+1][lrow] = a0.y; As[lk+2][lrow] = a0.z; As[lk+3][lrow] = a0.w;
        As[lk+4][lrow] = a1.x; As[lk+5][lrow] = a1.y; As[lk+6][lrow] = a1.z; As[lk+7][lrow] = a1.w;
        Ws[lk+0][lrow] = w0.x; Ws[lk+1][lrow] = w0.y; Ws[lk+2][lrow] = w0.z; Ws[lk+3][lrow] = w0.w;
        Ws[lk+4][lrow] = w1.x; Ws[lk+5][lrow] = w1.y; Ws[lk+6][lrow] = w1.z; Ws[lk+7][lrow] = w1.w;
        __syncthreads();

#pragma unroll
        for (int k = 0; k < 16; k++) {
            float ar[8], br[8];
            float4 t0 = *(const float4*)&As[k][ty * 8];
            float4 t1 = *(const float4*)&As[k][ty * 8 + 4];
            ar[0]=t0.x; ar[1]=t0.y; ar[2]=t0.z; ar[3]=t0.w;
            ar[4]=t1.x; ar[5]=t1.y; ar[6]=t1.z; ar[7]=t1.w;
            float4 u0 = *(const float4*)&Ws[k][tx * 8];
            float4 u1 = *(const float4*)&Ws[k][tx * 8 + 4];
            br[0]=u0.x; br[1]=u0.y; br[2]=u0.z; br[3]=u0.w;
            br[4]=u1.x; br[5]=u1.y; br[6]=u1.z; br[7]=u1.w;
#pragma unroll
            for (int i = 0; i < 8; i++)
#pragma unroll
                for (int j = 0; j < 8; j++)
                    acc[i][j] += ar[i] * br[j];
        }
    }

#pragma unroll
    for (int i = 0; i < 8; i++) {
        float* crow = C + (size_t)(m0 + ty * 8 + i) * N + n0 + tx * 8;
#pragma unroll
        for (int j = 0; j < 8; j++) {
            float v = acc[i][j];
            if (bias) v += bias[n0 + tx * 8 + j];
            crow[j] = v;
        }
    }
}

// ---------------------------------------------------------------------------
// Fused flash-style attention.
// Grid: (Lq/128, H, B), 128 threads; thread = one q row. KV tiles of 64.
// smem: Ks[64*64] | Vs[64*64] | Ps[128*65] (pos/scores/Q-staging, padded)
// ---------------------------------------------------------------------------
__global__ __launch_bounds__(128)
void attn_kernel(const float* __restrict__ Qb, const float* __restrict__ KVb,
                 const float* __restrict__ pos, float* __restrict__ Ob)
{
    extern __shared__ float sm[];
    float* Ks = sm;                 // 64*64
    float* Vs = sm + 64 * 64;       // 64*64
    float* Ps = sm + 2 * 64 * 64;   // 128*65 (padded rows)

    const int tid = threadIdx.x;
    const int b = blockIdx.z, h = blockIdx.y;
    const int q0 = blockIdx.x * 128;

    // Stage Q tile into Ps (coalesced), then pull this thread's row to regs
    const float* Qbase = Qb + ((size_t)(b * LQ + q0)) * DIMC + h * HDIM;
    for (int i = tid; i < 128 * 64; i += 128) {
        int r = i >> 6, c = i & 63;
        Ps[r * 65 + c] = Qbase[(size_t)r * DIMC + c];
    }
    __syncthreads();
    float Qr[64];
#pragma unroll
    for (int d = 0; d < 64; d++) Qr[d] = Ps[tid * 65 + d];

    float O[64];
#pragma unroll
    for (int d = 0; d < 64; d++) O[d] = 0.f;
    float mv = -1e30f, l = 0.f;

    const float* Kbase   = KVb + (size_t)b * LKV * (2 * DIMC) + h * HDIM;
    const float* Vbase   = Kbase + DIMC;
    const float* posbase = pos + ((size_t)(h * LQ + q0)) * LKV;
    float* myP = Ps + tid * 65;

    for (int kv0 = 0; kv0 < LKV; kv0 += 64) {
        __syncthreads();   // protect smem before overwrite
        for (int i = tid; i < 64 * 64; i += 128) {
            int r = i >> 6, c = i & 63;
            Ks[r * 64 + c] = Kbase[(size_t)(kv0 + r) * (2 * DIMC) + c];
            Vs[r * 64 + c] = Vbase[(size_t)(kv0 + r) * (2 * DIMC) + c];
        }
        for (int i = tid; i < 128 * 64; i += 128) {
            int r = i >> 6, c = i & 63;
            Ps[r * 65 + c] = posbase[(size_t)r * LKV + kv0 + c];
        }
        __syncthreads();

        // pass 1: scores + running max (scores parked in own Ps row)
        float tmax = mv;
#pragma unroll 2
        for (int kv = 0; kv < 64; kv++) {
            const float4* kr = (const float4*)(Ks + kv * 64);
            float s0 = 0.f, s1 = 0.f, s2 = 0.f, s3 = 0.f;
#pragma unroll
            for (int d4 = 0; d4 < 16; d4++) {
                float4 kk = kr[d4];
                s0 += Qr[4 * d4 + 0] * kk.x;
                s1 += Qr[4 * d4 + 1] * kk.y;
                s2 += Qr[4 * d4 + 2] * kk.z;
                s3 += Qr[4 * d4 + 3] * kk.w;
            }
            float s = (s0 + s1) + (s2 + s3);
            s = s * SCALE + myP[kv];
            myP[kv] = s;
            tmax = fmaxf(tmax, s);
        }

        // online softmax rescale
        float alpha = __expf(mv - tmax);
        mv = tmax;
        l *= alpha;
#pragma unroll
        for (int d = 0; d < 64; d++) O[d] *= alpha;

        // pass 2: exp + PV accumulate
        for (int kv = 0; kv < 64; kv++) {
            float p = __expf(myP[kv] - mv);
            l += p;
            const float4* vr = (const float4*)(Vs + kv * 64);
#pragma unroll
            for (int d4 = 0; d4 < 16; d4++) {
                float4 vv = vr[d4];
                O[4 * d4 + 0] += p * vv.x;
                O[4 * d4 + 1] += p * vv.y;
                O[4 * d4 + 2] += p * vv.z;
                O[4 * d4 + 3] += p * vv.w;
            }
        }
    }

    const float inv = 1.f / l;
    float* orow = Ob + ((size_t)(b * LQ + q0 + tid)) * DIMC + h * HDIM;
#pragma unroll
    for (int d = 0; d < 64; d++) orow[d] = O[d] * inv;
}

// ---------------------------------------------------------------------------
extern "C" void kernel_launch(void* const* d_in, const int* in_sizes, int n_in,
                              void* d_out, int out_size)
{
    (void)in_sizes; (void)n_in; (void)out_size;
    const float* q     = (const float*)d_in[0];
    const float* kv    = (const float*)d_in[1];
    const float* pos   = (const float*)d_in[2];
    const float* Wq    = (const float*)d_in[3];
    const float* Wkv   = (const float*)d_in[4];
    const float* Wproj = (const float*)d_in[5];
    const float* bproj = (const float*)d_in[6];
    float* out = (float*)d_out;

    float *gQ, *gKV, *gO;
    cudaGetSymbolAddress((void**)&gQ,  g_Q);
    cudaGetSymbolAddress((void**)&gKV, g_KV);
    cudaGetSymbolAddress((void**)&gO,  g_O);

    const int ATTN_SMEM = (2 * 64 * 64 + 128 * 65) * sizeof(float);  // 66048 B
    cudaFuncSetAttribute(attn_kernel, cudaFuncAttributeMaxDynamicSharedMemorySize, ATTN_SMEM);

    const int M = BATCH * LQ;   // 8192

    // Q = q @ Wq^T
    gemm_nt<<<dim3(DIMC / 128, M / 128), 256>>>(q, Wq, nullptr, gQ, M, DIMC, DIMC);
    // KV = kv @ Wkv^T  (cols [0,768)=K, [768,1536)=V)
    gemm_nt<<<dim3(2 * DIMC / 128, M / 128), 256>>>(kv, Wkv, nullptr, gKV, M, 2 * DIMC, DIMC);
    // fused attention
    attn_kernel<<<dim3(LQ / 128, NHEADS, BATCH), 128, ATTN_SMEM>>>(gQ, gKV, pos, gO);
    // out = O @ Wproj^T + bproj
    gemm_nt<<<dim3(DIMC / 128, M / 128), 256>>>(gO, Wproj, bproj, out, M, DIMC, DIMC);
}

// round 3
// speedup vs baseline: 1.4156x; 1.4156x over previous
#include <cuda_runtime.h>
#include <cuda_bf16.h>
#include <cstdint>
#include <cstddef>

// Problem constants
#define DIMC   768
#define NHEADS 12
#define HDIM   64
#define BATCH  8
#define LQ     1024
#define LKV    1024
#define SCALE  0.125f

#define MROWS  (BATCH * LQ)     // 8192

// fp32 scratch (attention I/O)
__device__ float g_Q [(size_t)MROWS * DIMC];
__device__ float g_KV[(size_t)MROWS * 2 * DIMC];
__device__ float g_O [(size_t)MROWS * DIMC];

// bf16 split scratch
__device__ __nv_bfloat16 g_qh [(size_t)MROWS * DIMC];
__device__ __nv_bfloat16 g_ql [(size_t)MROWS * DIMC];
__device__ __nv_bfloat16 g_kvh[(size_t)MROWS * DIMC];
__device__ __nv_bfloat16 g_kvl[(size_t)MROWS * DIMC];
__device__ __nv_bfloat16 g_oh [(size_t)MROWS * DIMC];
__device__ __nv_bfloat16 g_ol [(size_t)MROWS * DIMC];
__device__ __nv_bfloat16 g_wqh[(size_t)DIMC * DIMC];
__device__ __nv_bfloat16 g_wql[(size_t)DIMC * DIMC];
__device__ __nv_bfloat16 g_wkh[(size_t)2 * DIMC * DIMC];
__device__ __nv_bfloat16 g_wkl[(size_t)2 * DIMC * DIMC];
__device__ __nv_bfloat16 g_wph[(size_t)DIMC * DIMC];
__device__ __nv_bfloat16 g_wpl[(size_t)DIMC * DIMC];

// ---------------------------------------------------------------------------
__device__ __forceinline__ uint32_t smem_u32(const void* p) {
    uint32_t a;
    asm("{ .reg .u64 t; cvta.to.shared.u64 t, %1; cvt.u32.u64 %0, t; }" : "=r"(a) : "l"(p));
    return a;
}
__device__ __forceinline__ void ldsm4(uint32_t* r, uint32_t addr) {
    asm volatile("ldmatrix.sync.aligned.m8n8.x4.shared.b16 {%0,%1,%2,%3}, [%4];"
        : "=r"(r[0]), "=r"(r[1]), "=r"(r[2]), "=r"(r[3]) : "r"(addr));
}
__device__ __forceinline__ void mma16816(float* d, const uint32_t* a, const uint32_t* b) {
    asm volatile("mma.sync.aligned.m16n8k16.row.col.f32.bf16.bf16.f32 "
        "{%0,%1,%2,%3}, {%4,%5,%6,%7}, {%8,%9}, {%0,%1,%2,%3};"
        : "+f"(d[0]), "+f"(d[1]), "+f"(d[2]), "+f"(d[3])
        : "r"(a[0]), "r"(a[1]), "r"(a[2]), "r"(a[3]), "r"(b[0]), "r"(b[1]));
}
__device__ __forceinline__ void cp16(uint32_t dst, const void* src) {
    asm volatile("cp.async.cg.shared.global [%0], [%1], 16;" :: "r"(dst), "l"(src) : "memory");
}
#define CP_COMMIT() asm volatile("cp.async.commit_group;" ::: "memory")

// swizzled byte offset inside a 128B-row tile: row, c16 = 16B-column (0..7)
__device__ __forceinline__ uint32_t swz(int row, int c16) {
    return (uint32_t)(row * 128 + ((c16 ^ (row & 7)) << 4));
}

// stage one 128x64-bf16 buffer (16KB) via cp.async (per-thread 4x16B)
__device__ __forceinline__ void stage_buf(uint32_t sdst, const __nv_bfloat16* rowbase,
                                          int K, int k0, int crow, int chalf) {
    const __nv_bfloat16* src = rowbase + (size_t)crow * K + k0 + chalf * 8;
    uint32_t dbase = sdst + (uint32_t)crow * 128;
    int rx = crow & 7;
#pragma unroll
    for (int j = 0; j < 4; j++) {
        int c16 = chalf + j;
        cp16(dbase + (((c16 ^ rx)) << 4), src + j * 8);
    }
}

// ---------------------------------------------------------------------------
// C[M,N] = A[M,K] @ W[N,K]^T (+bias), bf16-split 3-pass via mma.sync.
// Grid (N/128, M/128), 256 threads. K-chunks of 64, 2-stage cp.async pipeline.
// ---------------------------------------------------------------------------
#define STG_STRIDE 65536
#define BUF_AH 0
#define BUF_AL 16384
#define BUF_WH 32768
#define BUF_WL 49152

__global__ __launch_bounds__(256, 1)
void gemm_mma(const __nv_bfloat16* __restrict__ Ah, const __nv_bfloat16* __restrict__ Al,
              const __nv_bfloat16* __restrict__ Wh, const __nv_bfloat16* __restrict__ Wl,
              const float* __restrict__ bias, float* __restrict__ C, int N, int K)
{
    extern __shared__ char sm[];
    const uint32_t smb = smem_u32(sm);
    const int tid = threadIdx.x;
    const int wid = tid >> 5, lane = tid & 31;
    const int wm = wid >> 2, wn = wid & 3;           // warp 64x32 tile
    const int m0 = blockIdx.y * 128, n0 = blockIdx.x * 128;

    const int crow = tid >> 1;
    const int chalf = (tid & 1) * 4;

    const __nv_bfloat16* Ahb = Ah + (size_t)m0 * K;
    const __nv_bfloat16* Alb = Al + (size_t)m0 * K;
    const __nv_bfloat16* Whb = Wh + (size_t)n0 * K;
    const __nv_bfloat16* Wlb = Wl + (size_t)n0 * K;

    // ldmatrix lane geometry
    const int g = lane >> 3, r = lane & 7;
    const int arl = (g & 1) * 8 + r;   // A row-in-16  (g0:0-7 klo, g1:8-15 klo, g2:0-7 khi, g3)
    const int acs = g >> 1;            // A k16 half
    const int brl = (g >> 1) * 8 + r;  // B row-in-16
    const int bcs = g & 1;             // B k16 half

    float acc[4][4][4];
#pragma unroll
    for (int i = 0; i < 4; i++)
#pragma unroll
        for (int j = 0; j < 4; j++)
#pragma unroll
            for (int k = 0; k < 4; k++) acc[i][j][k] = 0.f;

    const int NC = K >> 6;    // chunks of 64

    // prefetch chunk 0 -> stage 0
    {
        uint32_t sb = smb;
        stage_buf(sb + BUF_AH, Ahb, K, 0, crow, chalf);
        stage_buf(sb + BUF_AL, Alb, K, 0, crow, chalf);
        stage_buf(sb + BUF_WH, Whb, K, 0, crow, chalf);
        stage_buf(sb + BUF_WL, Wlb, K, 0, crow, chalf);
        CP_COMMIT();
    }

    for (int c = 0; c < NC; ++c) {
        if (c + 1 < NC) {
            uint32_t sb = smb + ((c + 1) & 1) * STG_STRIDE;
            int k0 = (c + 1) << 6;
            stage_buf(sb + BUF_AH, Ahb, K, k0, crow, chalf);
            stage_buf(sb + BUF_AL, Alb, K, k0, crow, chalf);
            stage_buf(sb + BUF_WH, Whb, K, k0, crow, chalf);
            stage_buf(sb + BUF_WL, Wlb, K, k0, crow, chalf);
            CP_COMMIT();
            asm volatile("cp.async.wait_group 1;" ::: "memory");
        } else {
            asm volatile("cp.async.wait_group 0;" ::: "memory");
        }
        __syncthreads();

        const uint32_t sb = smb + (c & 1) * STG_STRIDE;
        const uint32_t bAh = sb + BUF_AH, bAl = sb + BUF_AL;
        const uint32_t bWh = sb + BUF_WH, bWl = sb + BUF_WL;

#pragma unroll
        for (int s = 0; s < 4; ++s) {
            uint32_t afr[4][4], bh[2][4], bl[2][4];
#pragma unroll
            for (int mt = 0; mt < 4; ++mt)
                ldsm4(afr[mt], bAh + swz(wm * 64 + mt * 16 + arl, s * 2 + acs));
#pragma unroll
            for (int p = 0; p < 2; ++p)
                ldsm4(bh[p], bWh + swz(wn * 32 + p * 16 + brl, s * 2 + bcs));
#pragma unroll
            for (int p = 0; p < 2; ++p)
                ldsm4(bl[p], bWl + swz(wn * 32 + p * 16 + brl, s * 2 + bcs));

#pragma unroll
            for (int mt = 0; mt < 4; ++mt)
#pragma unroll
                for (int nt = 0; nt < 4; ++nt)
                    mma16816(acc[mt][nt], afr[mt], &bh[nt >> 1][(nt & 1) * 2]);
#pragma unroll
            for (int mt = 0; mt < 4; ++mt)
#pragma unroll
                for (int nt = 0; nt < 4; ++nt)
                    mma16816(acc[mt][nt], afr[mt], &bl[nt >> 1][(nt & 1) * 2]);
            // overwrite A frags with lo
#pragma unroll
            for (int mt = 0; mt < 4; ++mt)
                ldsm4(afr[mt], bAl + swz(wm * 64 + mt * 16 + arl, s * 2 + acs));
#pragma unroll
            for (int mt = 0; mt < 4; ++mt)
#pragma unroll
                for (int nt = 0; nt < 4; ++nt)
                    mma16816(acc[mt][nt], afr[mt], &bh[nt >> 1][(nt & 1) * 2]);
        }
        __syncthreads();
    }

    // epilogue
    const int er = lane >> 2, ec = (lane & 3) * 2;
#pragma unroll
    for (int mt = 0; mt < 4; ++mt) {
#pragma unroll
        for (int nt = 0; nt < 4; ++nt) {
            int grow = m0 + wm * 64 + mt * 16 + er;
            int gcol = n0 + wn * 32 + nt * 8 + ec;
            float b0 = 0.f, b1 = 0.f;
            if (bias) { b0 = bias[gcol]; b1 = bias[gcol + 1]; }
            float2 v0 = make_float2(acc[mt][nt][0] + b0, acc[mt][nt][1] + b1);
            float2 v1 = make_float2(acc[mt][nt][2] + b0, acc[mt][nt][3] + b1);
            *(float2*)(C + (size_t)grow * N + gcol) = v0;
            *(float2*)(C + (size_t)(grow + 8) * N + gcol) = v1;
        }
    }
}

// ---------------------------------------------------------------------------
// fp32 -> (hi, lo) bf16 split, vectorized x4
// ---------------------------------------------------------------------------
__global__ __launch_bounds__(256)
void cvt_split(const float4* __restrict__ in, uint2* __restrict__ hi,
               uint2* __restrict__ lo, int n4)
{
    int i = blockIdx.x * blockDim.x + threadIdx.x;
    if (i >= n4) return;
    float4 x = in[i];
    __nv_bfloat162 h01 = __floats2bfloat162_rn(x.x, x.y);
    __nv_bfloat162 h23 = __floats2bfloat162_rn(x.z, x.w);
    float r0 = x.x - __low2float(h01), r1 = x.y - __high2float(h01);
    float r2 = x.z - __low2float(h23), r3 = x.w - __high2float(h23);
    __nv_bfloat162 l01 = __floats2bfloat162_rn(r0, r1);
    __nv_bfloat162 l23 = __floats2bfloat162_rn(r2, r3);
    hi[i] = make_uint2(*(uint32_t*)&h01, *(uint32_t*)&h23);
    lo[i] = make_uint2(*(uint32_t*)&l01, *(uint32_t*)&l23);
}

// ---------------------------------------------------------------------------
// Fused flash-style attention (unchanged, known-good from R1).
// ---------------------------------------------------------------------------
__global__ __launch_bounds__(128)
void attn_kernel(const float* __restrict__ Qb, const float* __restrict__ KVb,
                 const float* __restrict__ pos, float* __restrict__ Ob)
{
    extern __shared__ float smf[];
    float* Ks = smf;
    float* Vs = smf + 64 * 64;
    float* Ps = smf + 2 * 64 * 64;

    const int tid = threadIdx.x;
    const int b = blockIdx.z, h = blockIdx.y;
    const int q0 = blockIdx.x * 128;

    const float* Qbase = Qb + ((size_t)(b * LQ + q0)) * DIMC + h * HDIM;
    for (int i = tid; i < 128 * 64; i += 128) {
        int rr = i >> 6, cc = i & 63;
        Ps[rr * 65 + cc] = Qbase[(size_t)rr * DIMC + cc];
    }
    __syncthreads();
    float Qr[64];
#pragma unroll
    for (int d = 0; d < 64; d++) Qr[d] = Ps[tid * 65 + d];

    float O[64];
#pragma unroll
    for (int d = 0; d < 64; d++) O[d] = 0.f;
    float mv = -1e30f, l = 0.f;

    const float* Kbase   = KVb + (size_t)b * LKV * (2 * DIMC) + h * HDIM;
    const float* Vbase   = Kbase + DIMC;
    const float* posbase = pos + ((size_t)(h * LQ + q0)) * LKV;
    float* myP = Ps + tid * 65;

    for (int kv0 = 0; kv0 < LKV; kv0 += 64) {
        __syncthreads();
        for (int i = tid; i < 64 * 64; i += 128) {
            int rr = i >> 6, cc = i & 63;
            Ks[rr * 64 + cc] = Kbase[(size_t)(kv0 + rr) * (2 * DIMC) + cc];
            Vs[rr * 64 + cc] = Vbase[(size_t)(kv0 + rr) * (2 * DIMC) + cc];
        }
        for (int i = tid; i < 128 * 64; i += 128) {
            int rr = i >> 6, cc = i & 63;
            Ps[rr * 65 + cc] = posbase[(size_t)rr * LKV + kv0 + cc];
        }
        __syncthreads();

        float tmax = mv;
#pragma unroll 2
        for (int kv = 0; kv < 64; kv++) {
            const float4* kr = (const float4*)(Ks + kv * 64);
            float s0 = 0.f, s1 = 0.f, s2 = 0.f, s3 = 0.f;
#pragma unroll
            for (int d4 = 0; d4 < 16; d4++) {
                float4 kk = kr[d4];
                s0 += Qr[4 * d4 + 0] * kk.x;
                s1 += Qr[4 * d4 + 1] * kk.y;
                s2 += Qr[4 * d4 + 2] * kk.z;
                s3 += Qr[4 * d4 + 3] * kk.w;
            }
            float s = (s0 + s1) + (s2 + s3);
            s = s * SCALE + myP[kv];
            myP[kv] = s;
            tmax = fmaxf(tmax, s);
        }

        float alpha = __expf(mv - tmax);
        mv = tmax;
        l *= alpha;
#pragma unroll
        for (int d = 0; d < 64; d++) O[d] *= alpha;

        for (int kv = 0; kv < 64; kv++) {
            float p = __expf(myP[kv] - mv);
            l += p;
            const float4* vr = (const float4*)(Vs + kv * 64);
#pragma unroll
            for (int d4 = 0; d4 < 16; d4++) {
                float4 vv = vr[d4];
                O[4 * d4 + 0] += p * vv.x;
                O[4 * d4 + 1] += p * vv.y;
                O[4 * d4 + 2] += p * vv.z;
                O[4 * d4 + 3] += p * vv.w;
            }
        }
    }

    const float inv = 1.f / l;
    float* orow = Ob + ((size_t)(b * LQ + q0 + tid)) * DIMC + h * HDIM;
#pragma unroll
    for (int d = 0; d < 64; d++) orow[d] = O[d] * inv;
}

// ---------------------------------------------------------------------------
extern "C" void kernel_launch(void* const* d_in, const int* in_sizes, int n_in,
                              void* d_out, int out_size)
{
    (void)in_sizes; (void)n_in; (void)out_size;
    const float* q     = (const float*)d_in[0];
    const float* kv    = (const float*)d_in[1];
    const float* pos   = (const float*)d_in[2];
    const float* Wq    = (const float*)d_in[3];
    const float* Wkv   = (const float*)d_in[4];
    const float* Wproj = (const float*)d_in[5];
    const float* bproj = (const float*)d_in[6];
    float* out = (float*)d_out;

    float *gQ, *gKV, *gO;
    cudaGetSymbolAddress((void**)&gQ,  g_Q);
    cudaGetSymbolAddress((void**)&gKV, g_KV);
    cudaGetSymbolAddress((void**)&gO,  g_O);
    __nv_bfloat16 *qh, *ql, *kvh, *kvl, *oh, *ol, *wqh, *wql, *wkh, *wkl, *wph, *wpl;
    cudaGetSymbolAddress((void**)&qh,  g_qh);   cudaGetSymbolAddress((void**)&ql,  g_ql);
    cudaGetSymbolAddress((void**)&kvh, g_kvh);  cudaGetSymbolAddress((void**)&kvl, g_kvl);
    cudaGetSymbolAddress((void**)&oh,  g_oh);   cudaGetSymbolAddress((void**)&ol,  g_ol);
    cudaGetSymbolAddress((void**)&wqh, g_wqh);  cudaGetSymbolAddress((void**)&wql, g_wql);
    cudaGetSymbolAddress((void**)&wkh, g_wkh);  cudaGetSymbolAddress((void**)&wkl, g_wkl);
    cudaGetSymbolAddress((void**)&wph, g_wph);  cudaGetSymbolAddress((void**)&wpl, g_wpl);

    static bool attr_done = false;
    if (!attr_done) {
        cudaFuncSetAttribute(gemm_mma, cudaFuncAttributeMaxDynamicSharedMemorySize, 2 * STG_STRIDE);
        cudaFuncSetAttribute(attn_kernel, cudaFuncAttributeMaxDynamicSharedMemorySize,
                             (2 * 64 * 64 + 128 * 65) * (int)sizeof(float));
        attr_done = true;
    }
    const int ATTN_SMEM = (2 * 64 * 64 + 128 * 65) * sizeof(float);
    const int GEMM_SMEM = 2 * STG_STRIDE;

    const int M = MROWS;

    auto cvt = [](const float* p, __nv_bfloat16* h, __nv_bfloat16* l, size_t n) {
        int n4 = (int)(n / 4);
        cvt_split<<<(n4 + 255) / 256, 256>>>((const float4*)p, (uint2*)h, (uint2*)l, n4);
    };

    // split inputs + weights
    cvt(q,     qh,  ql,  (size_t)M * DIMC);
    cvt(kv,    kvh, kvl, (size_t)M * DIMC);
    cvt(Wq,    wqh, wql, (size_t)DIMC * DIMC);
    cvt(Wkv,   wkh, wkl, (size_t)2 * DIMC * DIMC);
    cvt(Wproj, wph, wpl, (size_t)DIMC * DIMC);

    // Q = q @ Wq^T
    gemm_mma<<<dim3(DIMC / 128, M / 128), 256, GEMM_SMEM>>>(qh, ql, wqh, wql, nullptr, gQ, DIMC, DIMC);
    // KV = kv @ Wkv^T
    gemm_mma<<<dim3(2 * DIMC / 128, M / 128), 256, GEMM_SMEM>>>(kvh, kvl, wkh, wkl, nullptr, gKV, 2 * DIMC, DIMC);
    // attention
    attn_kernel<<<dim3(LQ / 128, NHEADS, BATCH), 128, ATTN_SMEM>>>(gQ, gKV, pos, gO);
    // split O, then out = O @ Wproj^T + bproj
    cvt(gO, oh, ol, (size_t)M * DIMC);
    gemm_mma<<<dim3(DIMC / 128, M / 128), 256, GEMM_SMEM>>>(oh, ol, wph, wpl, bproj, out, DIMC, DIMC);
}